// round 15
// baseline (speedup 1.0000x reference)
#include <cuda_runtime.h>
#include <cuda_bf16.h>

// DamerauLevenshtein: 32 queries (BSZ*SEQ, maxlen 14) vs 10000 words.
// One thread per (b,s,word); 16x16 uint8 DP matrix in smem, chunked-byte
// interleave -> lane-private banks for the dynamic transposition read.
// R12 = R10 (fused 1-launch counting sort, T=96 @ 9 blocks/SM, peeled last
// row, row cut i<=swl, sorted column cut j<=wlm) + software-pipelined
// transposition LDS: the d[k][l] load for iteration j+1 issues during
// iteration j (operands kreg[j], post-update db are final by then), hiding
// the 29-cycle LDS latency behind the min-chain ALU work.

#define T 96           // threads per block
#define ML 14          // max word / query length
#define WSTR 384       // byte stride between word-groups: (T*4)
#define RSTR 1536      // byte stride between DP rows: 4*WSTR

__device__ int g_perm[10240];  // sorted-position -> original word index
                               // fully rewritten every launch (replay-safe)

__global__ void sort_kernel(const int* __restrict__ wlen, int n) {
    __shared__ int sh[16];
    const int tid = threadIdx.x;
    if (tid < 16) sh[tid] = 0;
    __syncthreads();
    const int lane = tid & 31;
    const unsigned ltm = (1u << lane) - 1u;
    // histogram (warp-aggregated)
    for (int base = 0; base < n; base += 1024) {
        int i = base + tid;
        bool act = (i < n);
        unsigned mask = __ballot_sync(0xffffffffu, act);
        if (act) {
            int l = wlen[i];
            unsigned peers = __match_any_sync(mask, l);
            if (lane == (__ffs(peers) - 1)) atomicAdd(&sh[l], __popc(peers));
        }
    }
    __syncthreads();
    if (tid == 0) {           // exclusive scan of 16 bins
        int acc = 0;
#pragma unroll
        for (int l = 0; l < 16; l++) { int c = sh[l]; sh[l] = acc; acc += c; }
    }
    __syncthreads();
    // scatter (warp-aggregated; tie order within a bin is irrelevant to d_out)
    for (int base = 0; base < n; base += 1024) {
        int i = base + tid;
        bool act = (i < n);
        unsigned mask = __ballot_sync(0xffffffffu, act);
        if (act) {
            int l = wlen[i];
            unsigned peers = __match_any_sync(mask, l);
            int leader = __ffs(peers) - 1;
            int wbase = 0;
            if (lane == leader) wbase = atomicAdd(&sh[l], __popc(peers));
            wbase = __shfl_sync(peers, wbase, leader);
            g_perm[wbase + __popc(peers & ltm)] = i;
        }
    }
}

__device__ __forceinline__ int eoff(int e) {
    // byte offset (from this thread's base = sd + tid*4) of matrix element e
    return (e >> 2) * WSTR + (e & 3);
}

__global__ __launch_bounds__(T, 9)
void dl_kernel(const int* __restrict__ x,
               const int* __restrict__ words,
               const int* __restrict__ wlen,
               float* __restrict__ out,
               int n_words)
{
    __shared__ unsigned char sd[256 * T];   // 24 KB: 256 bytes per thread
    const int tid = threadIdx.x;
    const int bs  = blockIdx.y;                 // b*SEQ + s
    const int ws  = blockIdx.x * T + tid;       // sorted position
    const int wsr = (ws < n_words) ? ws : 0;
    const int orig = g_perm[wsr];               // original word index

    unsigned char* base = sd + tid * 4;

    // ---- load query string (15 ints, broadcast across block) ----
    int xq[ML + 1];
    const int* xp = x + bs * (ML + 1);
#pragma unroll
    for (int t = 0; t <= ML; t++) xq[t] = xp[t];

    // swl = argmax (first occurrence of max) -- uniform across the block
    int swl = 0, best = xq[0];
#pragma unroll
    for (int t = 1; t <= ML; t++)
        if (xq[t] > best) { best = xq[t]; swl = t; }

    // ---- load word (gather through the permutation; tiny, L2-resident) ----
    int wch[ML];
    const int* wp = words + orig * ML;
#pragma unroll
    for (int t = 0; t < ML; t++) wch[t] = wp[t];
    const int wl  = wlen[orig];
    const int wlm = __reduce_max_sync(0xffffffffu, wl);  // warp-uniform bound
    const int md  = swl + wl;                   // max_dist

    // ---- init shared matrix rows 0 and 1 (cols 0..15) ----
#pragma unroll
    for (int jj = 0; jj < 16; jj++) base[eoff(jj)] = (unsigned char)md;   // row 0
    base[eoff(16 + 0)] = (unsigned char)md;                                // d[1][0]
    base[eoff(16 + 1)] = 0;                                                // d[1][1]
#pragma unroll
    for (int jj = 2; jj < 16; jj++) {
        int v = (jj - 1 <= wl) ? (jj - 1) : 0;                             // wla
        base[eoff(16 + jj)] = (unsigned char)v;
    }

    // previous DP row in registers (indices 1..15 used); row = d[1][*]
    int row[16];
    row[1] = 0;
#pragma unroll
    for (int jj = 2; jj < 16; jj++) row[jj] = (jj - 1 <= wl) ? (jj - 1) : 0;

    // kreg[j-1] == da[word_char_j] : last i' < i with x[i'-1]==wch[j-1]
    int kreg[ML];
#pragma unroll
    for (int t = 0; t < ML; t++) kreg[t] = 0;

    // result register; for swl==0 the answer is d[1][wl+1] = wl
    int res = wl;

    // ---- regular rows i = 1 .. swl-1 (write rows 2..swl to smem) ----
    for (int i = 1; i < swl; i++) {
        const int xc = xq[i - 1];
        int db = 0;
        int prev_old = row[1];                  // old d[i][1]
        row[1] = i;                             // swl_row boundary d[i+1][1]
        unsigned char* rp = base + (i + 1) * RSTR;    // row (i+1) base
        rp[0] = (unsigned char)md;              // d[i+1][0]
        rp[1] = (unsigned char)i;               // d[i+1][1]

        // pipeline prologue: dtr for j=1 (k = kreg[0], l = 0)
        int kcur = kreg[0];
        int dtr  = (int)base[kcur * RSTR];

#pragma unroll
        for (int j = 1; j <= ML; j++) {
            if (j > wlm) break;                 // warp-uniform column cut
            const int k = kcur;                 // kreg[j-1] pre-update
            const int l = db;
            const bool eq  = (xc == wch[j - 1]);
            const int cost = eq ? 0 : 1;
            if (eq) { db = j; kreg[j - 1] = i; }

            // prefetch dtr for iteration j+1 (k'=kreg[j], l'=db post-update);
            // issued before this cell's STS -> latency overlapped with ALU.
            int dtr_n = 0;
            if (j < ML) {
                kcur  = kreg[j];
                dtr_n = (int)base[kcur * RSTR + (db >> 2) * WSTR + (db & 3)];
            }

            const int up = row[j + 1];             // old d[i][j+1]
            int v = min(up, row[j]) + 1;           // delete / insert
            v = min(v, prev_old + cost);           // substitution
            v = min(v, dtr + (i + j - 1) - k - l); // transposition
            prev_old = up;
            row[j + 1] = v;
            rp[((j + 1) >> 2) * WSTR + ((j + 1) & 3)] = (unsigned char)v;
            dtr = dtr_n;
        }
    }

    // ---- peeled last row i = swl (no smem writes; capture result) ----
    if (swl >= 1) {
        const int i  = swl;
        const int xc = xq[i - 1];
        int db = 0;
        int prev_old = row[1];                  // old d[i][1]
        int vprev = i;                          // new d[i+1][1] boundary

        int kcur = kreg[0];
        int dtr  = (int)base[kcur * RSTR];

#pragma unroll
        for (int j = 1; j <= ML; j++) {
            if (j > wlm) break;
            const int k = kcur;
            const int l = db;
            const bool eq  = (xc == wch[j - 1]);
            const int cost = eq ? 0 : 1;
            if (eq) db = j;                     // kreg update not needed

            int dtr_n = 0;
            if (j < ML) {
                kcur  = kreg[j];
                dtr_n = (int)base[kcur * RSTR + (db >> 2) * WSTR + (db & 3)];
            }

            const int up = row[j + 1];
            int v = min(up, vprev) + 1;
            v = min(v, prev_old + cost);
            v = min(v, dtr + (i + j - 1) - k - l);
            prev_old = up;
            vprev = v;
            if (j == wl) res = v;               // d[swl+1][wl+1]
            dtr = dtr_n;
        }
    }

    if (ws < n_words)
        out[bs * n_words + orig] = (float)res;
}

extern "C" void kernel_launch(void* const* d_in, const int* in_sizes, int n_in,
                              void* d_out, int out_size)
{
    const int* x     = (const int*)d_in[0];      // (BSZ, SEQ, 15) int32
    const int* words = (const int*)d_in[1];      // (N, 14) int32
    const int* wlen  = (const int*)d_in[2];      // (N,) int32
    const int n_words  = in_sizes[2];
    const int bs_total = in_sizes[0] / (ML + 1); // BSZ*SEQ = 32

    sort_kernel<<<1, 1024>>>(wlen, n_words);

    dim3 grid((n_words + T - 1) / T, bs_total);
    dl_kernel<<<grid, T>>>(x, words, wlen, (float*)d_out, n_words);
}